// round 12
// baseline (speedup 1.0000x reference)
#include <cuda_runtime.h>

typedef unsigned long long u64;

#define TPB 128
#define EPB 256   // elements per block (2 per thread)
// element strides in u64 units; 21 mod 16 = 5, 17 mod 16 = 1 (coprime 16)
// -> conflict-free LDS.64 across 16-lane phases
#define STRIDE10 21   // 20 u64 data (40 floats) + 1 pad
#define STRIDE8  17   // 16 u64 data (32 floats) + 1 pad

// ---- packed f32x2 helpers ----
__device__ __forceinline__ u64 pk2(float lo, float hi) {
    u64 r; asm("mov.b64 %0,{%1,%2};" : "=l"(r) : "f"(lo), "f"(hi)); return r;
}
__device__ __forceinline__ float2 unpk(u64 v) {
    float2 f; asm("mov.b64 {%0,%1},%2;" : "=f"(f.x), "=f"(f.y) : "l"(v)); return f;
}
__device__ __forceinline__ u64 fma2(u64 a, u64 b, u64 c) {
    u64 d; asm("fma.rn.f32x2 %0,%1,%2,%3;" : "=l"(d) : "l"(a), "l"(b), "l"(c)); return d;
}
__device__ __forceinline__ u64 relu2(u64 v) {
    float2 f = unpk(v);
    return pk2(fmaxf(f.x, 0.f), fmaxf(f.y, 0.f));
}

// ---- shared layout (u64 units) ----
#define O_EW1 0
#define O_EB1 100
#define O_EW2 110
#define O_EB2 210
#define O_EW3 220
#define O_EB3 230
#define O_XW1 231
#define O_XB1 295
#define O_XW2 303
#define O_XB2 367
#define O_XW3 375
#define O_XB3 383
#define O_CW1 384
#define O_CB1 484
#define O_CW2 494
#define O_CB2 594
#define O_CW3 604
#define O_CB3 614
#define O_NW  615
#define O_NB  616
#define NWTS  617
// input buffers: edge+cross live together; corner reuses the edge buffer
#define O_EDGE   624
#define O_CROSS  (O_EDGE + EPB * STRIDE10)           // 624 + 5376 = 6000
#define O_CORNER O_EDGE
#define SMEM_U64 (O_CROSS + EPB * STRIDE8)           // 6000 + 4352 = 10352
#define SMEM_BYTES (SMEM_U64 * 8)                    // 82816 -> 2 CTAs/SM

// 3-layer MLP over TWO elements x 4 slices (four f32x2 streams), interleaved
// so every weight LDS.64 feeds 4 fma2. Returns {sumA, sumB}.
template <int D>
__device__ __forceinline__ float2 mlp2(const u64* __restrict__ xeA,
                                       const u64* __restrict__ xeB,
                                       const u64* __restrict__ w1, const u64* __restrict__ bb1,
                                       const u64* __restrict__ w2, const u64* __restrict__ bb2,
                                       const u64* __restrict__ w3, const u64* __restrict__ bb3) {
    u64 xa0[D], xa1[D], xb0[D], xb1[D];
    u64 ha0[D], ha1[D], hb0[D], hb1[D];
#pragma unroll
    for (int i = 0; i < D; i++) {
        xa0[i] = xeA[i * 2]; xa1[i] = xeA[i * 2 + 1];
        xb0[i] = xeB[i * 2]; xb1[i] = xeB[i * 2 + 1];
    }
    // layer 1 + relu
#pragma unroll
    for (int o = 0; o < D; o++) {
        u64 b = bb1[o], sa0 = b, sa1 = b, sb0 = b, sb1 = b;
#pragma unroll
        for (int i = 0; i < D; i++) {
            u64 w = w1[o * D + i];
            sa0 = fma2(xa0[i], w, sa0);
            sa1 = fma2(xa1[i], w, sa1);
            sb0 = fma2(xb0[i], w, sb0);
            sb1 = fma2(xb1[i], w, sb1);
        }
        ha0[o] = relu2(sa0); ha1[o] = relu2(sa1);
        hb0[o] = relu2(sb0); hb1[o] = relu2(sb1);
    }
    // layer 2 + relu (write back into x arrays)
#pragma unroll
    for (int o = 0; o < D; o++) {
        u64 b = bb2[o], sa0 = b, sa1 = b, sb0 = b, sb1 = b;
#pragma unroll
        for (int i = 0; i < D; i++) {
            u64 w = w2[o * D + i];
            sa0 = fma2(ha0[i], w, sa0);
            sa1 = fma2(ha1[i], w, sa1);
            sb0 = fma2(hb0[i], w, sb0);
            sb1 = fma2(hb1[i], w, sb1);
        }
        xa0[o] = relu2(sa0); xa1[o] = relu2(sa1);
        xb0[o] = relu2(sb0); xb1[o] = relu2(sb1);
    }
    // layer 3 (linear, out dim 1)
    u64 b = bb3[0], sa0 = b, sa1 = b, sb0 = b, sb1 = b;
#pragma unroll
    for (int i = 0; i < D; i++) {
        u64 w = w3[i];
        sa0 = fma2(xa0[i], w, sa0);
        sa1 = fma2(xa1[i], w, sa1);
        sb0 = fma2(xb0[i], w, sb0);
        sb1 = fma2(xb1[i], w, sb1);
    }
    float2 fa0 = unpk(sa0), fa1 = unpk(sa1), fb0 = unpk(sb0), fb1 = unpk(sb1);
    float2 r;
    r.x = fa0.x + fa0.y + fa1.x + fa1.y;
    r.y = fb0.x + fb0.y + fb1.x + fb1.y;
    return r;
}

// Coalesced stage of EPB elements x (4*D) floats into shared, pair-interleaved:
// element e, feature i, slice s -> e*STRIDE*2 + i*4 + s (floats).
template <int D, int STRIDE>
__device__ __forceinline__ void stage2(const float* __restrict__ g, float* __restrict__ s, int tid) {
    const float4* g4 = (const float4*)g;
#pragma unroll
    for (int k = 0; k < 2 * D; k++) {
        int f = k * TPB + tid;          // float4 index, consecutive across threads
        float4 v = g4[f];
        int elem = f / D;
        int j = f - elem * D;
        float vv[4] = {v.x, v.y, v.z, v.w};
        float* base = s + elem * (STRIDE * 2);
#pragma unroll
        for (int c = 0; c < 4; c++) {
            int within = j * 4 + c;     // 0..4D-1, slice-major in gmem
            int sl = within / D;
            int i  = within - sl * D;
            base[i * 4 + sl] = vv[c];
        }
    }
}

__global__ __launch_bounds__(TPB, 2)
void osero_kernel(const float* __restrict__ edge, const float* __restrict__ cross,
                  const float* __restrict__ corner, const float* __restrict__ cn,
                  const float* __restrict__ eW1, const float* __restrict__ eb1,
                  const float* __restrict__ eW2, const float* __restrict__ eb2,
                  const float* __restrict__ eW3, const float* __restrict__ eb3,
                  const float* __restrict__ xW1, const float* __restrict__ xb1,
                  const float* __restrict__ xW2, const float* __restrict__ xb2,
                  const float* __restrict__ xW3, const float* __restrict__ xb3,
                  const float* __restrict__ cW1, const float* __restrict__ cb1,
                  const float* __restrict__ cW2, const float* __restrict__ cb2,
                  const float* __restrict__ cW3, const float* __restrict__ cb3,
                  const float* __restrict__ nW, const float* __restrict__ nb,
                  float* __restrict__ out) {
    extern __shared__ u64 dsm[];
    u64* swts = dsm;

    const int tid = threadIdx.x;
    const long long e0 = (long long)blockIdx.x * EPB;

    // ---- stage edge + cross (36 LDG.128 in flight per thread) ----
    stage2<10, STRIDE10>(edge  + e0 * 40, (float*)(dsm + O_EDGE),  tid);
    stage2<8,  STRIDE8 >(cross + e0 * 32, (float*)(dsm + O_CROSS), tid);
    const float cnA = cn[e0 + tid];
    const float cnB = cn[e0 + TPB + tid];

    // ---- stage weights, duplicated into both f32x2 lanes ----
    {
        auto cp = [&](int off, const float* src, int n) {
            for (int i = tid; i < n; i += TPB) { float v = src[i]; swts[off + i] = pk2(v, v); }
        };
        cp(O_EW1, eW1, 100); cp(O_EB1, eb1, 10);
        cp(O_EW2, eW2, 100); cp(O_EB2, eb2, 10);
        cp(O_EW3, eW3, 10);  cp(O_EB3, eb3, 1);
        cp(O_XW1, xW1, 64);  cp(O_XB1, xb1, 8);
        cp(O_XW2, xW2, 64);  cp(O_XB2, xb2, 8);
        cp(O_XW3, xW3, 8);   cp(O_XB3, xb3, 1);
        cp(O_CW1, cW1, 100); cp(O_CB1, cb1, 10);
        cp(O_CW2, cW2, 100); cp(O_CB2, cb2, 10);
        cp(O_CW3, cW3, 10);  cp(O_CB3, cb3, 1);
        cp(O_NW, nW, 1);     cp(O_NB, nb, 1);
    }

    __syncthreads();

    // elements: A = tid, B = tid + TPB (both strides keep LDS conflict-free)
    float2 acc = mlp2<10>(dsm + O_EDGE + tid * STRIDE10,
                          dsm + O_EDGE + (tid + TPB) * STRIDE10,
                          swts + O_EW1, swts + O_EB1, swts + O_EW2,
                          swts + O_EB2, swts + O_EW3, swts + O_EB3);
    {
        float2 t = mlp2<8>(dsm + O_CROSS + tid * STRIDE8,
                           dsm + O_CROSS + (tid + TPB) * STRIDE8,
                           swts + O_XW1, swts + O_XB1, swts + O_XW2,
                           swts + O_XB2, swts + O_XW3, swts + O_XB3);
        acc.x += t.x; acc.y += t.y;
    }

    __syncthreads();   // all reads of edge buffer done
    stage2<10, STRIDE10>(corner + e0 * 40, (float*)(dsm + O_CORNER), tid);
    __syncthreads();

    {
        float2 t = mlp2<10>(dsm + O_CORNER + tid * STRIDE10,
                            dsm + O_CORNER + (tid + TPB) * STRIDE10,
                            swts + O_CW1, swts + O_CB1, swts + O_CW2,
                            swts + O_CB2, swts + O_CW3, swts + O_CB3);
        acc.x += t.x; acc.y += t.y;
    }

    float2 nwv = unpk(swts[O_NW]);
    float2 nbv = unpk(swts[O_NB]);
    out[e0 + tid]       = acc.x + cnA * nwv.x + nbv.x;
    out[e0 + TPB + tid] = acc.y + cnB * nwv.x + nbv.x;
}

extern "C" void kernel_launch(void* const* d_in, const int* in_sizes, int n_in,
                              void* d_out, int out_size) {
    const float* edge   = (const float*)d_in[0];
    const float* cross  = (const float*)d_in[1];
    const float* corner = (const float*)d_in[2];
    const float* cn     = (const float*)d_in[3];
    const float* eW1 = (const float*)d_in[4];
    const float* eb1 = (const float*)d_in[5];
    const float* eW2 = (const float*)d_in[6];
    const float* eb2 = (const float*)d_in[7];
    const float* eW3 = (const float*)d_in[8];
    const float* eb3 = (const float*)d_in[9];
    const float* xW1 = (const float*)d_in[10];
    const float* xb1 = (const float*)d_in[11];
    const float* xW2 = (const float*)d_in[12];
    const float* xb2 = (const float*)d_in[13];
    const float* xW3 = (const float*)d_in[14];
    const float* xb3 = (const float*)d_in[15];
    const float* cW1 = (const float*)d_in[16];
    const float* cb1 = (const float*)d_in[17];
    const float* cW2 = (const float*)d_in[18];
    const float* cb2 = (const float*)d_in[19];
    const float* cW3 = (const float*)d_in[20];
    const float* cb3 = (const float*)d_in[21];
    const float* nW  = (const float*)d_in[22];
    const float* nb  = (const float*)d_in[23];

    int B = in_sizes[0] / 40;          // edge is [B,4,10]
    int blocks = B / EPB;              // 4096

    cudaFuncSetAttribute(osero_kernel,
                         cudaFuncAttributeMaxDynamicSharedMemorySize, SMEM_BYTES);

    osero_kernel<<<blocks, TPB, SMEM_BYTES>>>(edge, cross, corner, cn,
                                  eW1, eb1, eW2, eb2, eW3, eb3,
                                  xW1, xb1, xW2, xb2, xW3, xb3,
                                  cW1, cb1, cW2, cb2, cW3, cb3,
                                  nW, nb, (float*)d_out);
}

// round 13
// speedup vs baseline: 1.0812x; 1.0812x over previous
#include <cuda_runtime.h>

typedef unsigned long long u64;

#define TPB 128
// element strides in u64 units; EVEN so element bases are 16B-aligned for
// LDS.128. Conflict check (8-lane phases of LDS.128):
//   stride 22 u64 = 176B: banks l*44 mod 32 = {0,12,24,4,16,28,8,20} distinct
//   stride 18 u64 = 144B: banks l*36 mod 32 = {0,4,8,...,28}        distinct
#define STRIDE10 22   // 20 u64 data (40 floats) + 2 pad
#define STRIDE8  18   // 16 u64 data (32 floats) + 2 pad

// ---- packed f32x2 helpers ----
__device__ __forceinline__ u64 pk2(float lo, float hi) {
    u64 r; asm("mov.b64 %0,{%1,%2};" : "=l"(r) : "f"(lo), "f"(hi)); return r;
}
__device__ __forceinline__ float2 unpk(u64 v) {
    float2 f; asm("mov.b64 {%0,%1},%2;" : "=f"(f.x), "=f"(f.y) : "l"(v)); return f;
}
__device__ __forceinline__ u64 fma2(u64 a, u64 b, u64 c) {
    u64 d; asm("fma.rn.f32x2 %0,%1,%2,%3;" : "=l"(d) : "l"(a), "l"(b), "l"(c)); return d;
}
__device__ __forceinline__ u64 relu2(u64 v) {
    float2 f = unpk(v);
    return pk2(fmaxf(f.x, 0.f), fmaxf(f.y, 0.f));
}

// ---- shared layout (u64 units); all WEIGHT bases EVEN (16B-aligned) ----
#define O_EW1 0
#define O_EB1 100
#define O_EW2 110
#define O_EB2 210
#define O_EW3 220
#define O_EB3 230
#define O_XW1 232
#define O_XB1 296
#define O_XW2 304
#define O_XB2 368
#define O_XW3 376
#define O_XB3 384
#define O_CW1 386
#define O_CB1 486
#define O_CW2 496
#define O_CB2 596
#define O_CW3 606
#define O_CB3 616
#define O_NW  617
#define O_NB  618
// staged input buffers (all resident simultaneously -> ONE barrier)
#define O_EDGE   624
#define O_CROSS  (O_EDGE + TPB * STRIDE10)            // 624 + 2816 = 3440
#define O_CORNER (O_CROSS + TPB * STRIDE8)            // 3440 + 2304 = 5744
#define SMEM_U64 (O_CORNER + TPB * STRIDE10)          // 5744 + 2816 = 8560
#define SMEM_BYTES (SMEM_U64 * 8)                     // 68480 -> 3 CTAs/SM

// 3-layer MLP over 4 slices as two f32x2 pairs. All shared loads are LDS.128:
// one weight fetch (two duplicated weights) feeds 4 fma2; input pairs load as
// one ulonglong2. xe: u64 index i*2+p = {slice 2p, slice 2p+1}, feature i.
template <int D>
__device__ __forceinline__ float mlp_sum4(const u64* __restrict__ xe,
                                          const u64* __restrict__ w1, const u64* __restrict__ b1,
                                          const u64* __restrict__ w2, const u64* __restrict__ b2,
                                          const u64* __restrict__ w3, const u64* __restrict__ b3) {
    u64 x0[D], x1[D], h0[D], h1[D];
    const ulonglong2* xev = (const ulonglong2*)xe;
#pragma unroll
    for (int i = 0; i < D; i++) { ulonglong2 v = xev[i]; x0[i] = v.x; x1[i] = v.y; }
    // layer 1 + relu
#pragma unroll
    for (int o = 0; o < D; o++) {
        u64 b = b1[o], a0 = b, a1 = b;
        const ulonglong2* wv = (const ulonglong2*)(w1 + o * D);
#pragma unroll
        for (int i2 = 0; i2 < D / 2; i2++) {
            ulonglong2 w = wv[i2];
            a0 = fma2(x0[2 * i2],     w.x, a0);
            a1 = fma2(x1[2 * i2],     w.x, a1);
            a0 = fma2(x0[2 * i2 + 1], w.y, a0);
            a1 = fma2(x1[2 * i2 + 1], w.y, a1);
        }
        h0[o] = relu2(a0); h1[o] = relu2(a1);
    }
    // layer 2 + relu (write back into x arrays)
#pragma unroll
    for (int o = 0; o < D; o++) {
        u64 b = b2[o], a0 = b, a1 = b;
        const ulonglong2* wv = (const ulonglong2*)(w2 + o * D);
#pragma unroll
        for (int i2 = 0; i2 < D / 2; i2++) {
            ulonglong2 w = wv[i2];
            a0 = fma2(h0[2 * i2],     w.x, a0);
            a1 = fma2(h1[2 * i2],     w.x, a1);
            a0 = fma2(h0[2 * i2 + 1], w.y, a0);
            a1 = fma2(h1[2 * i2 + 1], w.y, a1);
        }
        x0[o] = relu2(a0); x1[o] = relu2(a1);
    }
    // layer 3 (linear, out dim 1)
    u64 b = b3[0], a0 = b, a1 = b;
    const ulonglong2* wv = (const ulonglong2*)w3;
#pragma unroll
    for (int i2 = 0; i2 < D / 2; i2++) {
        ulonglong2 w = wv[i2];
        a0 = fma2(x0[2 * i2],     w.x, a0);
        a1 = fma2(x1[2 * i2],     w.x, a1);
        a0 = fma2(x0[2 * i2 + 1], w.y, a0);
        a1 = fma2(x1[2 * i2 + 1], w.y, a1);
    }
    float2 f0 = unpk(a0), f1 = unpk(a1);
    return f0.x + f0.y + f1.x + f1.y;
}

// Coalesced stage of TPB elements x (4*D) floats from global into shared with
// pair-interleaved layout: element e, feature i, slice s -> e*STRIDE*2 + i*4 + s (floats).
template <int D, int STRIDE>
__device__ __forceinline__ void stage(const float* __restrict__ g, float* __restrict__ s, int tid) {
    const float4* g4 = (const float4*)g;
#pragma unroll
    for (int k = 0; k < D; k++) {
        int f = k * TPB + tid;          // float4 index, consecutive across threads
        float4 v = g4[f];
        int elem = f / D;
        int j = f - elem * D;           // float4 within element (0..D-1)
        float vv[4] = {v.x, v.y, v.z, v.w};
        float* base = s + elem * (STRIDE * 2);
#pragma unroll
        for (int c = 0; c < 4; c++) {
            int within = j * 4 + c;     // 0..4D-1, slice-major in gmem
            int sl = within / D;
            int i  = within - sl * D;
            base[i * 4 + sl] = vv[c];
        }
    }
}

__global__ __launch_bounds__(TPB, 3)
void osero_kernel(const float* __restrict__ edge, const float* __restrict__ cross,
                  const float* __restrict__ corner, const float* __restrict__ cn,
                  const float* __restrict__ eW1, const float* __restrict__ eb1,
                  const float* __restrict__ eW2, const float* __restrict__ eb2,
                  const float* __restrict__ eW3, const float* __restrict__ eb3,
                  const float* __restrict__ xW1, const float* __restrict__ xb1,
                  const float* __restrict__ xW2, const float* __restrict__ xb2,
                  const float* __restrict__ xW3, const float* __restrict__ xb3,
                  const float* __restrict__ cW1, const float* __restrict__ cb1,
                  const float* __restrict__ cW2, const float* __restrict__ cb2,
                  const float* __restrict__ cW3, const float* __restrict__ cb3,
                  const float* __restrict__ nW, const float* __restrict__ nb,
                  float* __restrict__ out) {
    extern __shared__ u64 dsm[];
    u64* swts = dsm;

    const int tid = threadIdx.x;
    const long long e0 = (long long)blockIdx.x * TPB;

    // ---- stage ALL inputs first: 30 LDG.128 in flight per thread ----
    stage<10, STRIDE10>(edge   + e0 * 40, (float*)(dsm + O_EDGE),   tid);
    stage<8,  STRIDE8 >(cross  + e0 * 32, (float*)(dsm + O_CROSS),  tid);
    stage<10, STRIDE10>(corner + e0 * 40, (float*)(dsm + O_CORNER), tid);
    const float cnv = cn[e0 + tid];

    // ---- stage weights, duplicated into both f32x2 lanes ----
    {
        auto cp = [&](int off, const float* src, int n) {
            for (int i = tid; i < n; i += TPB) { float v = src[i]; swts[off + i] = pk2(v, v); }
        };
        cp(O_EW1, eW1, 100); cp(O_EB1, eb1, 10);
        cp(O_EW2, eW2, 100); cp(O_EB2, eb2, 10);
        cp(O_EW3, eW3, 10);  cp(O_EB3, eb3, 1);
        cp(O_XW1, xW1, 64);  cp(O_XB1, xb1, 8);
        cp(O_XW2, xW2, 64);  cp(O_XB2, xb2, 8);
        cp(O_XW3, xW3, 8);   cp(O_XB3, xb3, 1);
        cp(O_CW1, cW1, 100); cp(O_CB1, cb1, 10);
        cp(O_CW2, cW2, 100); cp(O_CB2, cb2, 10);
        cp(O_CW3, cW3, 10);  cp(O_CB3, cb3, 1);
        cp(O_NW, nW, 1);     cp(O_NB, nb, 1);
    }

    __syncthreads();   // the ONLY barrier

    float acc = mlp_sum4<10>(dsm + O_EDGE + tid * STRIDE10,
                             swts + O_EW1, swts + O_EB1, swts + O_EW2,
                             swts + O_EB2, swts + O_EW3, swts + O_EB3);
    acc += mlp_sum4<8>(dsm + O_CROSS + tid * STRIDE8,
                       swts + O_XW1, swts + O_XB1, swts + O_XW2,
                       swts + O_XB2, swts + O_XW3, swts + O_XB3);
    acc += mlp_sum4<10>(dsm + O_CORNER + tid * STRIDE10,
                        swts + O_CW1, swts + O_CB1, swts + O_CW2,
                        swts + O_CB2, swts + O_CW3, swts + O_CB3);

    float2 nwv = unpk(swts[O_NW]);
    float2 nbv = unpk(swts[O_NB]);
    acc += cnv * nwv.x + nbv.x;
    out[e0 + tid] = acc;
}

extern "C" void kernel_launch(void* const* d_in, const int* in_sizes, int n_in,
                              void* d_out, int out_size) {
    const float* edge   = (const float*)d_in[0];
    const float* cross  = (const float*)d_in[1];
    const float* corner = (const float*)d_in[2];
    const float* cn     = (const float*)d_in[3];
    const float* eW1 = (const float*)d_in[4];
    const float* eb1 = (const float*)d_in[5];
    const float* eW2 = (const float*)d_in[6];
    const float* eb2 = (const float*)d_in[7];
    const float* eW3 = (const float*)d_in[8];
    const float* eb3 = (const float*)d_in[9];
    const float* xW1 = (const float*)d_in[10];
    const float* xb1 = (const float*)d_in[11];
    const float* xW2 = (const float*)d_in[12];
    const float* xb2 = (const float*)d_in[13];
    const float* xW3 = (const float*)d_in[14];
    const float* xb3 = (const float*)d_in[15];
    const float* cW1 = (const float*)d_in[16];
    const float* cb1 = (const float*)d_in[17];
    const float* cW2 = (const float*)d_in[18];
    const float* cb2 = (const float*)d_in[19];
    const float* cW3 = (const float*)d_in[20];
    const float* cb3 = (const float*)d_in[21];
    const float* nW  = (const float*)d_in[22];
    const float* nb  = (const float*)d_in[23];

    int B = in_sizes[0] / 40;          // edge is [B,4,10]
    int blocks = B / TPB;              // 8192

    cudaFuncSetAttribute(osero_kernel,
                         cudaFuncAttributeMaxDynamicSharedMemorySize, SMEM_BYTES);

    osero_kernel<<<blocks, TPB, SMEM_BYTES>>>(edge, cross, corner, cn,
                                  eW1, eb1, eW2, eb2, eW3, eb3,
                                  xW1, xb1, xW2, xb2, xW3, xb3,
                                  cW1, cb1, cW2, cb2, cW3, cb3,
                                  nW, nb, (float*)d_out);
}

// round 15
// speedup vs baseline: 1.2681x; 1.1728x over previous
#include <cuda_runtime.h>

typedef unsigned long long u64;

#define TPB 128
// element strides in u64 units; 21 mod 16 = 5, 17 mod 16 = 1 (coprime 16)
// -> conflict-free scalar LDS.64 across 16-lane phases (R10-proven)
#define STRIDE10 21
#define STRIDE8  17

// ---- packed f32x2 helpers ----
__device__ __forceinline__ u64 pk2(float lo, float hi) {
    u64 r; asm("mov.b64 %0,{%1,%2};" : "=l"(r) : "f"(lo), "f"(hi)); return r;
}
__device__ __forceinline__ float2 unpk(u64 v) {
    float2 f; asm("mov.b64 {%0,%1},%2;" : "=f"(f.x), "=f"(f.y) : "l"(v)); return f;
}
__device__ __forceinline__ u64 fma2(u64 a, u64 b, u64 c) {
    u64 d; asm("fma.rn.f32x2 %0,%1,%2,%3;" : "=l"(d) : "l"(a), "l"(b), "l"(c)); return d;
}
__device__ __forceinline__ u64 relu2(u64 v) {
    float2 f = unpk(v);
    return pk2(fmaxf(f.x, 0.f), fmaxf(f.y, 0.f));
}

// ---- constant-bank layout (u64 units): layer-2/3 weights + biases ----
#define C_EW2 0
#define C_EB2 100
#define C_XW2 110
#define C_XB2 174
#define C_CW2 182
#define C_CB2 282
#define C_EW3 292
#define C_EB3 302
#define C_XW3 303
#define C_XB3 311
#define C_CW3 312
#define C_CB3 322
#define C_NW  323
#define C_NB  324
#define NCONST 325

__constant__ u64 cwt[NCONST];
__device__ u64 g_stage[NCONST];   // staging for D2D copy into cwt

// ---- shared layout (u64 units): layer-1 weights only + staged inputs ----
#define S_EW1 0
#define S_EB1 100
#define S_XW1 110
#define S_XB1 174
#define S_CW1 182
#define S_CB1 282
#define NSW   296
#define O_EDGE   NSW
#define O_CROSS  (O_EDGE + TPB * STRIDE10)            // 296 + 2688 = 2984
#define O_CORNER (O_CROSS + TPB * STRIDE8)            // 2984 + 2176 = 5160
#define SMEM_U64 (O_CORNER + TPB * STRIDE10)          // 5160 + 2688 = 7848
#define SMEM_BYTES (SMEM_U64 * 8)                     // 62784 -> 3 CTAs/SM

// 3-layer MLP over 4 slices as two f32x2 pairs sharing each weight fetch.
// Layer 1 weights come from SHARED (crossbar); layers 2/3 from CONSTANT
// (separate const-cache port) -> the two memory paths run in parallel.
template <int D, int CW2, int CB2, int CW3, int CB3>
__device__ __forceinline__ float mlp_sum4(const u64* __restrict__ xe,
                                          const u64* __restrict__ w1,
                                          const u64* __restrict__ b1) {
    u64 x0[D], x1[D], h0[D], h1[D];
#pragma unroll
    for (int i = 0; i < D; i++) { x0[i] = xe[i * 2]; x1[i] = xe[i * 2 + 1]; }
    // layer 1 + relu (weights via smem broadcast LDS.64)
#pragma unroll
    for (int o = 0; o < D; o++) {
        u64 b = b1[o], a0 = b, a1 = b;
#pragma unroll
        for (int i = 0; i < D; i++) {
            u64 w = w1[o * D + i];
            a0 = fma2(x0[i], w, a0);
            a1 = fma2(x1[i], w, a1);
        }
        h0[o] = relu2(a0); h1[o] = relu2(a1);
    }
    // layer 2 + relu (weights via constant port, immediate offsets)
#pragma unroll
    for (int o = 0; o < D; o++) {
        u64 b = cwt[CB2 + o], a0 = b, a1 = b;
#pragma unroll
        for (int i = 0; i < D; i++) {
            u64 w = cwt[CW2 + o * D + i];
            a0 = fma2(h0[i], w, a0);
            a1 = fma2(h1[i], w, a1);
        }
        x0[o] = relu2(a0); x1[o] = relu2(a1);
    }
    // layer 3 (linear, out dim 1; constant port)
    u64 b = cwt[CB3], a0 = b, a1 = b;
#pragma unroll
    for (int i = 0; i < D; i++) {
        u64 w = cwt[CW3 + i];
        a0 = fma2(x0[i], w, a0);
        a1 = fma2(x1[i], w, a1);
    }
    float2 f0 = unpk(a0), f1 = unpk(a1);
    return f0.x + f0.y + f1.x + f1.y;
}

// Coalesced stage of TPB elements x (4*D) floats into shared, pair-interleaved:
// element e, feature i, slice s -> e*STRIDE*2 + i*4 + s (floats).
template <int D, int STRIDE>
__device__ __forceinline__ void stage(const float* __restrict__ g, float* __restrict__ s, int tid) {
    const float4* g4 = (const float4*)g;
#pragma unroll
    for (int k = 0; k < D; k++) {
        int f = k * TPB + tid;
        float4 v = g4[f];
        int elem = f / D;
        int j = f - elem * D;
        float vv[4] = {v.x, v.y, v.z, v.w};
        float* base = s + elem * (STRIDE * 2);
#pragma unroll
        for (int c = 0; c < 4; c++) {
            int within = j * 4 + c;     // 0..4D-1, slice-major in gmem
            int sl = within / D;
            int i  = within - sl * D;
            base[i * 4 + sl] = vv[c];
        }
    }
}

// Prep kernel: duplicate layer-2/3 weights into g_stage as {w,w} u64.
__global__ void osero_prep(const float* __restrict__ eW2, const float* __restrict__ eb2,
                           const float* __restrict__ eW3, const float* __restrict__ eb3,
                           const float* __restrict__ xW2, const float* __restrict__ xb2,
                           const float* __restrict__ xW3, const float* __restrict__ xb3,
                           const float* __restrict__ cW2, const float* __restrict__ cb2,
                           const float* __restrict__ cW3, const float* __restrict__ cb3,
                           const float* __restrict__ nW,  const float* __restrict__ nb) {
    int tid = threadIdx.x;
    auto dup = [&](int off, const float* src, int n) {
        for (int i = tid; i < n; i += blockDim.x) { float v = src[i]; g_stage[off + i] = pk2(v, v); }
    };
    dup(C_EW2, eW2, 100); dup(C_EB2, eb2, 10);
    dup(C_XW2, xW2, 64);  dup(C_XB2, xb2, 8);
    dup(C_CW2, cW2, 100); dup(C_CB2, cb2, 10);
    dup(C_EW3, eW3, 10);  dup(C_EB3, eb3, 1);
    dup(C_XW3, xW3, 8);   dup(C_XB3, xb3, 1);
    dup(C_CW3, cW3, 10);  dup(C_CB3, cb3, 1);
    dup(C_NW,  nW,  1);   dup(C_NB,  nb,  1);
}

__global__ __launch_bounds__(TPB, 3)
void osero_kernel(const float* __restrict__ edge, const float* __restrict__ cross,
                  const float* __restrict__ corner, const float* __restrict__ cn,
                  const float* __restrict__ eW1, const float* __restrict__ eb1,
                  const float* __restrict__ xW1, const float* __restrict__ xb1,
                  const float* __restrict__ cW1, const float* __restrict__ cb1,
                  float* __restrict__ out) {
    extern __shared__ u64 dsm[];
    u64* swts = dsm;

    const int tid = threadIdx.x;
    const long long e0 = (long long)blockIdx.x * TPB;

    // ---- stage ALL inputs first: 30 LDG.128 in flight per thread ----
    stage<10, STRIDE10>(edge   + e0 * 40, (float*)(dsm + O_EDGE),   tid);
    stage<8,  STRIDE8 >(cross  + e0 * 32, (float*)(dsm + O_CROSS),  tid);
    stage<10, STRIDE10>(corner + e0 * 40, (float*)(dsm + O_CORNER), tid);
    const float cnv = cn[e0 + tid];

    // ---- stage layer-1 weights (duplicated into both f32x2 lanes) ----
    {
        auto cp = [&](int off, const float* src, int n) {
            for (int i = tid; i < n; i += TPB) { float v = src[i]; swts[off + i] = pk2(v, v); }
        };
        cp(S_EW1, eW1, 100); cp(S_EB1, eb1, 10);
        cp(S_XW1, xW1, 64);  cp(S_XB1, xb1, 8);
        cp(S_CW1, cW1, 100); cp(S_CB1, cb1, 10);
    }

    __syncthreads();   // the ONLY barrier

    float acc = mlp_sum4<10, C_EW2, C_EB2, C_EW3, C_EB3>(
                    dsm + O_EDGE + tid * STRIDE10, swts + S_EW1, swts + S_EB1);
    acc += mlp_sum4<8, C_XW2, C_XB2, C_XW3, C_XB3>(
                    dsm + O_CROSS + tid * STRIDE8, swts + S_XW1, swts + S_XB1);
    acc += mlp_sum4<10, C_CW2, C_CB2, C_CW3, C_CB3>(
                    dsm + O_CORNER + tid * STRIDE10, swts + S_CW1, swts + S_CB1);

    float2 nwv = unpk(cwt[C_NW]);
    float2 nbv = unpk(cwt[C_NB]);
    acc += cnv * nwv.x + nbv.x;
    out[e0 + tid] = acc;
}

extern "C" void kernel_launch(void* const* d_in, const int* in_sizes, int n_in,
                              void* d_out, int out_size) {
    const float* edge   = (const float*)d_in[0];
    const float* cross  = (const float*)d_in[1];
    const float* corner = (const float*)d_in[2];
    const float* cn     = (const float*)d_in[3];
    const float* eW1 = (const float*)d_in[4];
    const float* eb1 = (const float*)d_in[5];
    const float* eW2 = (const float*)d_in[6];
    const float* eb2 = (const float*)d_in[7];
    const float* eW3 = (const float*)d_in[8];
    const float* eb3 = (const float*)d_in[9];
    const float* xW1 = (const float*)d_in[10];
    const float* xb1 = (const float*)d_in[11];
    const float* xW2 = (const float*)d_in[12];
    const float* xb2 = (const float*)d_in[13];
    const float* xW3 = (const float*)d_in[14];
    const float* xb3 = (const float*)d_in[15];
    const float* cW1 = (const float*)d_in[16];
    const float* cb1 = (const float*)d_in[17];
    const float* cW2 = (const float*)d_in[18];
    const float* cb2 = (const float*)d_in[19];
    const float* cW3 = (const float*)d_in[20];
    const float* cb3 = (const float*)d_in[21];
    const float* nW  = (const float*)d_in[22];
    const float* nb  = (const float*)d_in[23];

    int B = in_sizes[0] / 40;          // edge is [B,4,10]
    int blocks = B / TPB;              // 8192

    // 1) duplicate layer-2/3 weights into staging buffer (device side)
    osero_prep<<<1, 128>>>(eW2, eb2, eW3, eb3, xW2, xb2, xW3, xb3,
                           cW2, cb2, cW3, cb3, nW, nb);

    // 2) fill the constant bank. MUST resolve real device addresses for both
    //    symbols (passing the symbol itself as src was the R13 bug).
    void* cwt_dev = nullptr;
    void* stage_dev = nullptr;
    cudaGetSymbolAddress(&cwt_dev, cwt);
    cudaGetSymbolAddress(&stage_dev, g_stage);
    cudaMemcpyAsync(cwt_dev, stage_dev, NCONST * sizeof(u64),
                    cudaMemcpyDeviceToDevice);

    // 3) main kernel
    cudaFuncSetAttribute(osero_kernel,
                         cudaFuncAttributeMaxDynamicSharedMemorySize, SMEM_BYTES);
    osero_kernel<<<blocks, TPB, SMEM_BYTES>>>(edge, cross, corner, cn,
                                              eW1, eb1, xW1, xb1, cW1, cb1,
                                              (float*)d_out);
}